// round 7
// baseline (speedup 1.0000x reference)
#include <cuda_runtime.h>
#include <cstdint>

// Problem shape (static per reference): N=2048, L=512, D=256, B=256
#define N_PROT 2048
#define L_SEQ  512
#define D_DIM  256
#define B_SEG  256

// Scratch (__device__ globals are zero-initialized at module load; the
// finalizer restores them to zero each launch, keeping the invariant
// across graph replays).
__device__ float g_acc[B_SEG * D_DIM];   // segment sums
__device__ int   g_done[B_SEG];          // CTAs-arrived counter per segment

// Dtype-robust key fetch. keys buffer is either int32[2048] or int64[2048].
// Sorted keys in [0,256) with every segment non-empty => last key == 255.
//   int32 layout: word[2047] == 255
//   int64 layout: word[2047] == high word of element 1023 == 0
__device__ __forceinline__ int load_key(const int* k32, bool is32, int n) {
    int key = is32 ? __ldg(&k32[n]) : __ldg(&k32[2 * n]);
    return min(max(key, 0), B_SEG - 1);   // never form a wild address
}

// One CTA per protein. 256 threads: thread t owns float4-column (t&63),
// row-phase t>>6. Inner loop batches 16 independent LDG.128 per thread
// (MLP=16). __launch_bounds__(256, 2) gives a 128-reg budget so all 16
// loads stay live (R5: default budget collapses MLP to 4; R6: occ-4/MLP-8
// raised BW despite halved occupancy -> occupancy is not the binding
// resource, queue depth per thread is). Per-SM outstanding depth conserved:
// 2 CTA x 256 x 16 == 4 CTA x 256 x 8. Solo-CTA ceiling ~2x -> smaller
// end-of-grid drain tail.
// Last CTA of each (sorted) segment finalizes: spin until peers' atomics
// landed, divide, write out, reset scratch for the next graph replay.
__global__ __launch_bounds__(256, 2) void pool_fused_kernel(
    const float* __restrict__ embeds,    // [N, L, D] fp32
    const int* __restrict__ keys_raw,    // int32 view of batch_keys
    float* __restrict__ out              // [B, D] fp32
) {
    const int n = blockIdx.x;
    const int t = threadIdx.x;
    const bool is32 = (__ldg(&keys_raw[N_PROT - 1]) == (B_SEG - 1));
    const int key = load_key(keys_raw, is32, n);
    const bool is_last =
        (n == N_PROT - 1) || (load_key(keys_raw, is32, n + 1) != key);

    // ---- streaming partial sum (HBM-bound) ----
    const float4* __restrict__ row =
        (const float4*)(embeds + (size_t)n * (L_SEQ * D_DIM));
    const int c  = t & 63;   // float4 column (0..63)
    const int r0 = t >> 6;   // row-phase (0..3)

    float4 acc0 = make_float4(0.f, 0.f, 0.f, 0.f);
    float4 acc1 = make_float4(0.f, 0.f, 0.f, 0.f);
    float4 acc2 = make_float4(0.f, 0.f, 0.f, 0.f);
    float4 acc3 = make_float4(0.f, 0.f, 0.f, 0.f);
    // rows visited: r0, r0+4, ..., 128 rows per thread; batch 16 per outer
    // iteration (outer stride 64 rows), 8 outer iterations total.
    for (int l = r0; l < L_SEQ; l += 64) {
        float4 v[16];
        #pragma unroll
        for (int k = 0; k < 16; k++)
            v[k] = __ldg(&row[(l + 4 * k) * (D_DIM / 4) + c]);
        #pragma unroll
        for (int k = 0; k < 16; k += 4) {
            acc0.x += v[k].x;   acc0.y += v[k].y;
            acc0.z += v[k].z;   acc0.w += v[k].w;
            acc1.x += v[k+1].x; acc1.y += v[k+1].y;
            acc1.z += v[k+1].z; acc1.w += v[k+1].w;
            acc2.x += v[k+2].x; acc2.y += v[k+2].y;
            acc2.z += v[k+2].z; acc2.w += v[k+2].w;
            acc3.x += v[k+3].x; acc3.y += v[k+3].y;
            acc3.z += v[k+3].z; acc3.w += v[k+3].w;
        }
    }
    float4 acc = make_float4(acc0.x + acc1.x + acc2.x + acc3.x,
                             acc0.y + acc1.y + acc2.y + acc3.y,
                             acc0.z + acc1.z + acc2.z + acc3.z,
                             acc0.w + acc1.w + acc2.w + acc3.w);

    __shared__ float4 sdata[256];
    sdata[t] = acc;
    __syncthreads();

    if (t < 64) {
        float4 a = sdata[t];
        float4 b = sdata[t + 64];
        float4 e = sdata[t + 128];
        float4 f = sdata[t + 192];
        float* dst = g_acc + key * D_DIM + t * 4;
        atomicAdd(dst + 0, a.x + b.x + e.x + f.x);
        atomicAdd(dst + 1, a.y + b.y + e.y + f.y);
        atomicAdd(dst + 2, a.z + b.z + e.z + f.z);
        atomicAdd(dst + 3, a.w + b.w + e.w + f.w);
        __threadfence();   // release: my g_acc atomics visible before signal
    }
    __syncthreads();

    if (t == 0) atomicAdd(&g_done[key], 1);

    if (!is_last) return;

    // ---- finalizer (exactly one CTA per segment) ----
    __shared__ int s_count;
    if (t == 0) {
        // first index of this segment in the sorted keys
        int lo = 0, hi = n;
        while (lo < hi) {
            int mid = (lo + hi) >> 1;
            if (load_key(keys_raw, is32, mid) < key) lo = mid + 1;
            else hi = mid;
        }
        const int count = n - lo + 1;      // proteins in this segment
        // acquire: wait for all peers' signals
        while (atomicAdd(&g_done[key], 0) < count) __nanosleep(64);
        __threadfence();
        g_done[key] = 0;                   // reset for next replay
        s_count = count;
    }
    __syncthreads();

    const float inv = 1.0f / ((float)s_count * (float)L_SEQ);
    const int i = key * D_DIM + t;         // one column per thread
    const float sum = atomicAdd(&g_acc[i], 0.0f);   // L2-coherent read
    out[i] = sum * inv;
    g_acc[i] = 0.0f;                       // reset for next replay
}

extern "C" void kernel_launch(void* const* d_in, const int* in_sizes, int n_in,
                              void* d_out, int out_size) {
    const float* embeds = (const float*)d_in[0];
    const int*   keys   = (const int*)d_in[1];   // int32 view; dtype detected in-kernel
    float*       out    = (float*)d_out;

    pool_fused_kernel<<<N_PROT, 256>>>(embeds, keys, out);
}

// round 8
// speedup vs baseline: 1.0075x; 1.0075x over previous
#include <cuda_runtime.h>
#include <cstdint>

// Problem shape (static per reference): N=2048, L=512, D=256, B=256
#define N_PROT 2048
#define L_SEQ  512
#define D_DIM  256
#define B_SEG  256

// Scratch (__device__ globals are zero-initialized at module load; the
// finalizer restores them to zero each launch, keeping the invariant
// across graph replays).
__device__ float g_acc[B_SEG * D_DIM];   // segment sums
__device__ int   g_done[B_SEG];          // CTAs-arrived counter per segment

// Dtype-robust key fetch. keys buffer is either int32[2048] or int64[2048].
// Sorted keys in [0,256) with every segment non-empty => last key == 255.
//   int32 layout: word[2047] == 255
//   int64 layout: word[2047] == high word of element 1023 == 0
__device__ __forceinline__ int load_key(const int* k32, bool is32, int n) {
    int key = is32 ? __ldg(&k32[n]) : __ldg(&k32[2 * n]);
    return min(max(key, 0), B_SEG - 1);   // never form a wild address
}

// One CTA per protein. 256 threads: thread t owns float4-column (t&63),
// row-phase t>>6. Inner loop: 8 independent LDG.128 per thread (MLP=8,
// the measured sweet spot — R7 showed MLP=16 is flat: per-warp LDG queue
// M_max~55 is already full at 8). __launch_bounds__(256,4) = 64-reg budget
// keeps all 8 loads live. Loads use __ldcs (evict-first streaming): the
// 1 GiB stream has zero reuse, so don't let it churn L2 at normal priority.
// Last CTA of each (sorted) segment finalizes: spin until peers' atomics
// landed, divide, write out, reset scratch for the next graph replay.
__global__ __launch_bounds__(256, 4) void pool_fused_kernel(
    const float* __restrict__ embeds,    // [N, L, D] fp32
    const int* __restrict__ keys_raw,    // int32 view of batch_keys
    float* __restrict__ out              // [B, D] fp32
) {
    const int n = blockIdx.x;
    const int t = threadIdx.x;
    const bool is32 = (__ldg(&keys_raw[N_PROT - 1]) == (B_SEG - 1));
    const int key = load_key(keys_raw, is32, n);
    const bool is_last =
        (n == N_PROT - 1) || (load_key(keys_raw, is32, n + 1) != key);

    // ---- streaming partial sum (HBM-bound) ----
    const float4* __restrict__ row =
        (const float4*)(embeds + (size_t)n * (L_SEQ * D_DIM));
    const int c  = t & 63;   // float4 column (0..63)
    const int r0 = t >> 6;   // row-phase (0..3)

    float4 acc0 = make_float4(0.f, 0.f, 0.f, 0.f);
    float4 acc1 = make_float4(0.f, 0.f, 0.f, 0.f);
    float4 acc2 = make_float4(0.f, 0.f, 0.f, 0.f);
    float4 acc3 = make_float4(0.f, 0.f, 0.f, 0.f);
    // rows visited: r0, r0+4, ..., 128 per thread; batch 8 per outer iter.
    for (int l = r0; l < L_SEQ; l += 32) {
        float4 v0 = __ldcs(&row[(l +  0) * (D_DIM / 4) + c]);
        float4 v1 = __ldcs(&row[(l +  4) * (D_DIM / 4) + c]);
        float4 v2 = __ldcs(&row[(l +  8) * (D_DIM / 4) + c]);
        float4 v3 = __ldcs(&row[(l + 12) * (D_DIM / 4) + c]);
        float4 v4 = __ldcs(&row[(l + 16) * (D_DIM / 4) + c]);
        float4 v5 = __ldcs(&row[(l + 20) * (D_DIM / 4) + c]);
        float4 v6 = __ldcs(&row[(l + 24) * (D_DIM / 4) + c]);
        float4 v7 = __ldcs(&row[(l + 28) * (D_DIM / 4) + c]);
        acc0.x += v0.x; acc0.y += v0.y; acc0.z += v0.z; acc0.w += v0.w;
        acc1.x += v1.x; acc1.y += v1.y; acc1.z += v1.z; acc1.w += v1.w;
        acc2.x += v2.x; acc2.y += v2.y; acc2.z += v2.z; acc2.w += v2.w;
        acc3.x += v3.x; acc3.y += v3.y; acc3.z += v3.z; acc3.w += v3.w;
        acc0.x += v4.x; acc0.y += v4.y; acc0.z += v4.z; acc0.w += v4.w;
        acc1.x += v5.x; acc1.y += v5.y; acc1.z += v5.z; acc1.w += v5.w;
        acc2.x += v6.x; acc2.y += v6.y; acc2.z += v6.z; acc2.w += v6.w;
        acc3.x += v7.x; acc3.y += v7.y; acc3.z += v7.z; acc3.w += v7.w;
    }
    float4 acc = make_float4(acc0.x + acc1.x + acc2.x + acc3.x,
                             acc0.y + acc1.y + acc2.y + acc3.y,
                             acc0.z + acc1.z + acc2.z + acc3.z,
                             acc0.w + acc1.w + acc2.w + acc3.w);

    __shared__ float4 sdata[256];
    sdata[t] = acc;
    __syncthreads();

    if (t < 64) {
        float4 a = sdata[t];
        float4 b = sdata[t + 64];
        float4 e = sdata[t + 128];
        float4 f = sdata[t + 192];
        float* dst = g_acc + key * D_DIM + t * 4;
        atomicAdd(dst + 0, a.x + b.x + e.x + f.x);
        atomicAdd(dst + 1, a.y + b.y + e.y + f.y);
        atomicAdd(dst + 2, a.z + b.z + e.z + f.z);
        atomicAdd(dst + 3, a.w + b.w + e.w + f.w);
        __threadfence();   // release: my g_acc atomics visible before signal
    }
    __syncthreads();

    if (t == 0) atomicAdd(&g_done[key], 1);

    if (!is_last) return;

    // ---- finalizer (exactly one CTA per segment) ----
    __shared__ int s_count;
    if (t == 0) {
        // first index of this segment in the sorted keys
        int lo = 0, hi = n;
        while (lo < hi) {
            int mid = (lo + hi) >> 1;
            if (load_key(keys_raw, is32, mid) < key) lo = mid + 1;
            else hi = mid;
        }
        const int count = n - lo + 1;      // proteins in this segment
        // acquire: wait for all peers' signals
        while (atomicAdd(&g_done[key], 0) < count) __nanosleep(64);
        __threadfence();
        g_done[key] = 0;                   // reset for next replay
        s_count = count;
    }
    __syncthreads();

    const float inv = 1.0f / ((float)s_count * (float)L_SEQ);
    const int i = key * D_DIM + t;         // one column per thread
    const float sum = atomicAdd(&g_acc[i], 0.0f);   // L2-coherent read
    out[i] = sum * inv;
    g_acc[i] = 0.0f;                       // reset for next replay
}

extern "C" void kernel_launch(void* const* d_in, const int* in_sizes, int n_in,
                              void* d_out, int out_size) {
    const float* embeds = (const float*)d_in[0];
    const int*   keys   = (const int*)d_in[1];   // int32 view; dtype detected in-kernel
    float*       out    = (float*)d_out;

    pool_fused_kernel<<<N_PROT, 256>>>(embeds, keys, out);
}

// round 9
// speedup vs baseline: 1.0077x; 1.0002x over previous
#include <cuda_runtime.h>
#include <cstdint>

// Problem shape (static per reference): N=2048, L=512, D=256, B=256
#define N_PROT 2048
#define L_SEQ  512
#define D_DIM  256
#define B_SEG  256

// Scratch (__device__ globals are zero-initialized at module load; the
// finalizer restores them to zero each launch, keeping the invariant
// across graph replays).
__device__ float g_acc[B_SEG * D_DIM];   // segment sums (16B-aligned rows)
__device__ int   g_done[B_SEG];          // CTAs-arrived counter per segment

// Dtype-robust key fetch. keys buffer is either int32[2048] or int64[2048].
// Sorted keys in [0,256) with every segment non-empty => last key == 255.
//   int32 layout: word[2047] == 255
//   int64 layout: word[2047] == high word of element 1023 == 0
__device__ __forceinline__ int load_key(const int* k32, bool is32, int n) {
    int key = is32 ? __ldg(&k32[n]) : __ldg(&k32[2 * n]);
    return min(max(key, 0), B_SEG - 1);   // never form a wild address
}

// One CTA per protein. 256 threads: thread t owns float4-column (t&63),
// row-phase t>>6. Inner loop: 8 independent LDG.128 per thread (MLP=8,
// the measured sweet spot; R7 showed MLP=16 flat — per-warp LDG queue full
// at 8). __launch_bounds__(256,4) = 64-reg budget keeps all 8 loads live.
// __ldcs streaming loads (R8: +1% DRAM) — zero-reuse 1 GiB stream.
// Accumulation uses ONE vector atomicAdd(float4) per thread instead of 4
// scalars: atomic lane-ops share LTS slots with the data stream (R4
// quantified ~4%/4x-atomics), so 4x fewer lane-ops trims LTS contention.
// Last CTA of each (sorted) segment finalizes: spin until peers' atomics
// landed, divide, write out, reset scratch for the next graph replay.
__global__ __launch_bounds__(256, 4) void pool_fused_kernel(
    const float* __restrict__ embeds,    // [N, L, D] fp32
    const int* __restrict__ keys_raw,    // int32 view of batch_keys
    float* __restrict__ out              // [B, D] fp32
) {
    const int n = blockIdx.x;
    const int t = threadIdx.x;
    const bool is32 = (__ldg(&keys_raw[N_PROT - 1]) == (B_SEG - 1));
    const int key = load_key(keys_raw, is32, n);
    const bool is_last =
        (n == N_PROT - 1) || (load_key(keys_raw, is32, n + 1) != key);

    // ---- streaming partial sum (HBM/LTS-bound) ----
    const float4* __restrict__ row =
        (const float4*)(embeds + (size_t)n * (L_SEQ * D_DIM));
    const int c  = t & 63;   // float4 column (0..63)
    const int r0 = t >> 6;   // row-phase (0..3)

    float4 acc0 = make_float4(0.f, 0.f, 0.f, 0.f);
    float4 acc1 = make_float4(0.f, 0.f, 0.f, 0.f);
    float4 acc2 = make_float4(0.f, 0.f, 0.f, 0.f);
    float4 acc3 = make_float4(0.f, 0.f, 0.f, 0.f);
    // rows visited: r0, r0+4, ..., 128 per thread; batch 8 per outer iter.
    for (int l = r0; l < L_SEQ; l += 32) {
        float4 v0 = __ldcs(&row[(l +  0) * (D_DIM / 4) + c]);
        float4 v1 = __ldcs(&row[(l +  4) * (D_DIM / 4) + c]);
        float4 v2 = __ldcs(&row[(l +  8) * (D_DIM / 4) + c]);
        float4 v3 = __ldcs(&row[(l + 12) * (D_DIM / 4) + c]);
        float4 v4 = __ldcs(&row[(l + 16) * (D_DIM / 4) + c]);
        float4 v5 = __ldcs(&row[(l + 20) * (D_DIM / 4) + c]);
        float4 v6 = __ldcs(&row[(l + 24) * (D_DIM / 4) + c]);
        float4 v7 = __ldcs(&row[(l + 28) * (D_DIM / 4) + c]);
        acc0.x += v0.x; acc0.y += v0.y; acc0.z += v0.z; acc0.w += v0.w;
        acc1.x += v1.x; acc1.y += v1.y; acc1.z += v1.z; acc1.w += v1.w;
        acc2.x += v2.x; acc2.y += v2.y; acc2.z += v2.z; acc2.w += v2.w;
        acc3.x += v3.x; acc3.y += v3.y; acc3.z += v3.z; acc3.w += v3.w;
        acc0.x += v4.x; acc0.y += v4.y; acc0.z += v4.z; acc0.w += v4.w;
        acc1.x += v5.x; acc1.y += v5.y; acc1.z += v5.z; acc1.w += v5.w;
        acc2.x += v6.x; acc2.y += v6.y; acc2.z += v6.z; acc2.w += v6.w;
        acc3.x += v7.x; acc3.y += v7.y; acc3.z += v7.z; acc3.w += v7.w;
    }
    float4 acc = make_float4(acc0.x + acc1.x + acc2.x + acc3.x,
                             acc0.y + acc1.y + acc2.y + acc3.y,
                             acc0.z + acc1.z + acc2.z + acc3.z,
                             acc0.w + acc1.w + acc2.w + acc3.w);

    __shared__ float4 sdata[256];
    sdata[t] = acc;
    __syncthreads();

    if (t < 64) {
        float4 a = sdata[t];
        float4 b = sdata[t + 64];
        float4 e = sdata[t + 128];
        float4 f = sdata[t + 192];
        float4 r = make_float4(a.x + b.x + e.x + f.x,
                               a.y + b.y + e.y + f.y,
                               a.z + b.z + e.z + f.z,
                               a.w + b.w + e.w + f.w);
        // single 16B vector atomic (sm_90+): 1 LTS lane-op instead of 4
        float4* dst = (float4*)(g_acc + key * D_DIM + t * 4);
        atomicAdd(dst, r);
        __threadfence();   // release: my g_acc atomic visible before signal
    }
    __syncthreads();

    if (t == 0) atomicAdd(&g_done[key], 1);

    if (!is_last) return;

    // ---- finalizer (exactly one CTA per segment) ----
    __shared__ int s_count;
    if (t == 0) {
        // first index of this segment in the sorted keys
        int lo = 0, hi = n;
        while (lo < hi) {
            int mid = (lo + hi) >> 1;
            if (load_key(keys_raw, is32, mid) < key) lo = mid + 1;
            else hi = mid;
        }
        const int count = n - lo + 1;      // proteins in this segment
        // acquire: wait for all peers' signals
        while (atomicAdd(&g_done[key], 0) < count) __nanosleep(64);
        __threadfence();
        g_done[key] = 0;                   // reset for next replay
        s_count = count;
    }
    __syncthreads();

    const float inv = 1.0f / ((float)s_count * (float)L_SEQ);
    const int i = key * D_DIM + t;         // one column per thread
    const float sum = atomicAdd(&g_acc[i], 0.0f);   // L2-coherent read
    out[i] = sum * inv;
    g_acc[i] = 0.0f;                       // reset for next replay
}

extern "C" void kernel_launch(void* const* d_in, const int* in_sizes, int n_in,
                              void* d_out, int out_size) {
    const float* embeds = (const float*)d_in[0];
    const int*   keys   = (const int*)d_in[1];   // int32 view; dtype detected in-kernel
    float*       out    = (float*)d_out;

    pool_fused_kernel<<<N_PROT, 256>>>(embeds, keys, out);
}